// round 4
// baseline (speedup 1.0000x reference)
#include <cuda_runtime.h>

#define H   768
#define H4  192            // float4 per row
#define NROWS_F 32768
#define NROWS_E 4096
#define NINFU 0xff800000u

// ---------------- scratch (__device__ globals: allocation-free) ----------------
__device__ __align__(16) float g_colmax[H];
__device__ __align__(16) float g_qw[H];      // fact_Q @ W
__device__ __align__(16) float g_v[H];       // (W @ eacc)/SE
__device__ __align__(16) float g_eacc[H];    // unnormalized elements_p_
__device__ __align__(16) float g_facc[H];    // unnormalized fact_
__device__ float g_SE, g_SF;                 // softmax denominators
__device__ float g_dmaxE, g_dmaxF;           // global dot maxima
__device__ float g_dE[NROWS_E];
__device__ float g_dF[NROWS_F];

// ---------------- helpers ----------------
__device__ __forceinline__ void atomicMaxFloat(float* addr, float val) {
    if (val >= 0.0f) atomicMax((int*)addr, __float_as_int(val));
    else             atomicMin((unsigned int*)addr, __float_as_uint(val));
}
__device__ __forceinline__ float warpReduceSum(float v) {
    #pragma unroll
    for (int o = 16; o; o >>= 1) v += __shfl_xor_sync(0xffffffffu, v, o);
    return v;
}

// ---------------- kernels ----------------

__global__ void init_kernel() {
    int t = threadIdx.x;   // 768
    g_colmax[t] = __uint_as_float(NINFU);
    g_qw[t] = 0.0f; g_eacc[t] = 0.0f; g_facc[t] = 0.0f;
    if (t == 0) {
        g_SE = 0.0f; g_SF = 0.0f;
        g_dmaxE = __uint_as_float(NINFU);
        g_dmaxF = __uint_as_float(NINFU);
    }
}

// column max: blockDim=192 so (idx % H4) is invariant under grid stride
__global__ void colmax_kernel(const float4* __restrict__ X, int n4) {
    int idx = blockIdx.x * 192 + threadIdx.x;
    int stride = gridDim.x * 192;
    float4 m = make_float4(__uint_as_float(NINFU), __uint_as_float(NINFU),
                           __uint_as_float(NINFU), __uint_as_float(NINFU));
    #pragma unroll 4
    for (int i = idx; i < n4; i += stride) {
        float4 x = X[i];
        m.x = fmaxf(m.x, x.x); m.y = fmaxf(m.y, x.y);
        m.z = fmaxf(m.z, x.z); m.w = fmaxf(m.w, x.w);
    }
    int c = (idx % H4) * 4;
    atomicMaxFloat(&g_colmax[c + 0], m.x);
    atomicMaxFloat(&g_colmax[c + 1], m.y);
    atomicMaxFloat(&g_colmax[c + 2], m.z);
    atomicMaxFloat(&g_colmax[c + 3], m.w);
}

// qw[j] = sum_h colmax[h] * W[h, j]   grid (3, 24)
__global__ void qw_kernel(const float* __restrict__ W) {
    int j  = blockIdx.x * 256 + threadIdx.x;
    int h0 = blockIdx.y * 32;
    float a = 0.0f;
    #pragma unroll 8
    for (int i = 0; i < 32; i++)
        a += g_colmax[h0 + i] * W[(size_t)(h0 + i) * H + j];
    atomicAdd(&g_qw[j], a);
}

// dots: d[r] = X[r] . v ; block-reduced atomicMax into global max
template <bool FACT>
__global__ void __launch_bounds__(256)
dot_kernel(const float4* __restrict__ X, int rows) {
    const float4* vsrc = (const float4*)(FACT ? g_v : g_qw);
    float* dout = FACT ? g_dF : g_dE;
    int lane = threadIdx.x & 31;
    int wid  = threadIdx.x >> 5;
    int gw   = (blockIdx.x * 256 + threadIdx.x) >> 5;
    int nw   = (gridDim.x * 256) >> 5;

    float4 vr[6];
    #pragma unroll
    for (int k = 0; k < 6; k++) vr[k] = vsrc[lane + 32 * k];

    float mw = __uint_as_float(NINFU);
    for (int r = gw; r < rows; r += nw) {
        const float4* xr = X + (size_t)r * H4;
        float p = 0.0f;
        #pragma unroll
        for (int k = 0; k < 6; k++) {
            float4 x = xr[lane + 32 * k];
            p += x.x * vr[k].x + x.y * vr[k].y + x.z * vr[k].z + x.w * vr[k].w;
        }
        p = warpReduceSum(p);
        if (lane == 0) dout[r] = p;
        mw = fmaxf(mw, p);
    }
    __shared__ float sm[8];
    if (lane == 0) sm[wid] = mw;
    __syncthreads();
    if (threadIdx.x == 0) {
        float b = sm[0];
        #pragma unroll
        for (int i = 1; i < 8; i++) b = fmaxf(b, sm[i]);
        atomicMaxFloat(FACT ? &g_dmaxF : &g_dmaxE, b);
    }
}

// weighted sum: acc += exp(d[r]-Dmax) * X[r] ; s += exp(d[r]-Dmax)
// no shuffles, no cross-row serial dependence -> pure streaming
template <bool FACT>
__global__ void __launch_bounds__(256)
wsum_kernel(const float4* __restrict__ X, int rows) {
    const float* dsrc = FACT ? g_dF : g_dE;
    float Dmax = FACT ? g_dmaxF : g_dmaxE;
    int lane = threadIdx.x & 31;
    int wid  = threadIdx.x >> 5;
    int gw   = (blockIdx.x * 256 + threadIdx.x) >> 5;
    int nw   = (gridDim.x * 256) >> 5;

    float4 acc[6];
    #pragma unroll
    for (int k = 0; k < 6; k++) acc[k] = make_float4(0.f, 0.f, 0.f, 0.f);
    float s = 0.0f;

    for (int r = gw; r < rows; r += nw) {
        float w = __expf(dsrc[r] - Dmax);
        const float4* xr = X + (size_t)r * H4;
        #pragma unroll
        for (int k = 0; k < 6; k++) {
            float4 x = xr[lane + 32 * k];
            acc[k].x += w * x.x; acc[k].y += w * x.y;
            acc[k].z += w * x.z; acc[k].w += w * x.w;
        }
        if (lane == 0) s += w;
    }

    __shared__ float4 sh[8][H4];       // 24 KB
    __shared__ float  ss[8];
    #pragma unroll
    for (int k = 0; k < 6; k++) sh[wid][lane + 32 * k] = acc[k];
    if (lane == 0) ss[wid] = s;
    __syncthreads();

    if (threadIdx.x < H4) {
        float4 a = sh[0][threadIdx.x];
        #pragma unroll
        for (int w = 1; w < 8; w++) {
            float4 b = sh[w][threadIdx.x];
            a.x += b.x; a.y += b.y; a.z += b.z; a.w += b.w;
        }
        float* dst = FACT ? g_facc : g_eacc;
        int c = threadIdx.x * 4;
        atomicAdd(&dst[c + 0], a.x); atomicAdd(&dst[c + 1], a.y);
        atomicAdd(&dst[c + 2], a.z); atomicAdd(&dst[c + 3], a.w);
    }
    if (threadIdx.x == 0) {
        float t = ss[0];
        #pragma unroll
        for (int i = 1; i < 8; i++) t += ss[i];
        atomicAdd(FACT ? &g_SF : &g_SE, t);
    }
}

// v[h] = (W[h,:] . eacc) / SE    one warp per row; 96 blocks x 256
__global__ void v_kernel(const float4* __restrict__ W4) {
    int warp = blockIdx.x * 8 + (threadIdx.x >> 5);
    int lane = threadIdx.x & 31;
    const float4* row = W4 + (size_t)warp * H4;
    const float4* e = (const float4*)g_eacc;
    float p = 0.0f;
    #pragma unroll
    for (int k = 0; k < 6; k++) {
        float4 a = row[lane + 32 * k], b = e[lane + 32 * k];
        p += a.x * b.x + a.y * b.y + a.z * b.z + a.w * b.w;
    }
    p = warpReduceSum(p);
    if (lane == 0) g_v[warp] = p / g_SE;
}

__global__ void copyout_kernel(float* __restrict__ out, int out_size) {
    int i = blockIdx.x * blockDim.x + threadIdx.x;
    if (i >= out_size) return;
    out[i] = (i < H) ? g_facc[i] / g_SF : g_eacc[i - H] / g_SE;
}

// ---------------- launch ----------------
extern "C" void kernel_launch(void* const* d_in, const int* in_sizes, int n_in,
                              void* d_out, int out_size) {
    const float *fact = nullptr, *ep = nullptr, *W = nullptr;
    int N = 0, M = 0;
    for (int i = 0; i < n_in; i++) {
        long long sz = in_sizes[i];
        if (sz == (long long)H * H)           W    = (const float*)d_in[i];
        else if (sz == (long long)4096 * H) { ep   = (const float*)d_in[i]; M = 4096; }
        else                                { fact = (const float*)d_in[i]; N = (int)(sz / H); }
    }
    const float4* fact4 = (const float4*)fact;
    const float4* ep4   = (const float4*)ep;
    float* out = (float*)d_out;

    init_kernel<<<1, 768>>>();
    colmax_kernel<<<888, 192>>>(fact4, N * H4);            // pass 1 over fact (DRAM)
    qw_kernel<<<dim3(3, 24), 256>>>(W);                    // qw = fact_Q @ W

    dot_kernel<false><<<512, 256>>>(ep4, M);               // ep dots + max
    wsum_kernel<false><<<512, 256>>>(ep4, M);              // -> g_eacc, g_SE

    v_kernel<<<96, 256>>>((const float4*)W);               // v = (W @ eacc)/SE

    dot_kernel<true><<<2048, 256>>>(fact4, N);             // pass 2 over fact (L2-hot)
    wsum_kernel<true><<<1024, 256>>>(fact4, N);            // pass 3 over fact (L2-hot)

    copyout_kernel<<<(out_size + 255) / 256, 256>>>(out, out_size);
}

// round 6
// speedup vs baseline: 1.4386x; 1.4386x over previous
#include <cuda_runtime.h>

#define H   768
#define H4  192
#define NINFU 0xff800000u

// ---------------- scratch (__device__ globals: allocation-free) ----------------
__device__ __align__(16) float g_colmax[H];
__device__ __align__(16) float g_qw[H];          // fact_Q @ W
__device__ __align__(16) float g_v[H];           // W @ elements_p_
__device__ float g_pm[1024];                     // per-block running max
__device__ float g_ps[1024];                     // per-block running sum
__device__ __align__(16) float g_pacc[1024 * H]; // per-block weighted accumulators (3 MB)

// ---------------- helpers ----------------
__device__ __forceinline__ void atomicMaxFloat(float* addr, float val) {
    if (val >= 0.0f) atomicMax((int*)addr, __float_as_int(val));
    else             atomicMin((unsigned int*)addr, __float_as_uint(val));
}
__device__ __forceinline__ float warpReduceSum(float v) {
    #pragma unroll
    for (int o = 16; o; o >>= 1) v += __shfl_xor_sync(0xffffffffu, v, o);
    return v;
}

// ---------------- kernels ----------------

// zero d_out + g_qw, -inf g_colmax
__global__ void init_kernel(float* __restrict__ out) {
    int t = threadIdx.x;   // 768
    g_colmax[t] = __uint_as_float(NINFU);
    g_qw[t] = 0.0f;
    out[t] = 0.0f;
    out[t + H] = 0.0f;
}

// column max over fact: blockDim=192, grid=1024, stride keeps column fixed.
__global__ void __launch_bounds__(192)
colmax_kernel(const float4* __restrict__ X, int n4) {
    int idx = blockIdx.x * 192 + threadIdx.x;
    const int stride = 1024 * 192;
    float ninf = __uint_as_float(NINFU);
    float4 m = make_float4(ninf, ninf, ninf, ninf);
    int i = idx;
    for (; i + 7 * stride < n4; i += 8 * stride) {   // 8 independent loads
        float4 x[8];
        #pragma unroll
        for (int g = 0; g < 8; g++) x[g] = X[i + g * stride];
        #pragma unroll
        for (int g = 0; g < 8; g++) {
            m.x = fmaxf(m.x, x[g].x); m.y = fmaxf(m.y, x[g].y);
            m.z = fmaxf(m.z, x[g].z); m.w = fmaxf(m.w, x[g].w);
        }
    }
    for (; i < n4; i += stride) {
        float4 x = X[i];
        m.x = fmaxf(m.x, x.x); m.y = fmaxf(m.y, x.y);
        m.z = fmaxf(m.z, x.z); m.w = fmaxf(m.w, x.w);
    }
    int c = threadIdx.x * 4;   // column class fixed per thread
    atomicMaxFloat(&g_colmax[c + 0], m.x);
    atomicMaxFloat(&g_colmax[c + 1], m.y);
    atomicMaxFloat(&g_colmax[c + 2], m.z);
    atomicMaxFloat(&g_colmax[c + 3], m.w);
}

// qw[j] = sum_h colmax[h] * W[h, j]   grid (3, 24), coalesced over j
__global__ void qw_kernel(const float* __restrict__ W) {
    int j  = blockIdx.x * 256 + threadIdx.x;
    int h0 = blockIdx.y * 32;
    float a = 0.0f;
    #pragma unroll 8
    for (int i = 0; i < 32; i++)
        a += g_colmax[h0 + i] * W[(size_t)(h0 + i) * H + j];
    atomicAdd(&g_qw[j], a);
}

// Block-cooperative fused dots + online softmax + weighted sum.
// blockDim = 192 (thread = float4 column). 8 rows per macro-iter.
// USE_V selects the projection vector *inside device code* (g_v vs g_qw) —
// passing a __device__ symbol address from host is invalid (R5 bug).
template <bool USE_V>
__global__ void __launch_bounds__(192)
fused_kernel(const float4* __restrict__ X, int macro_iters) {
    const float4* vsrc = (const float4*)(USE_V ? g_v : g_qw);
    int c    = threadIdx.x;
    int wid  = c >> 5;          // 0..5
    int lane = c & 31;

    __shared__ float sp[8][192];   // per-thread partial dots
    __shared__ float sd[8];        // reduced row dots
    __shared__ float sw[9];        // w[0..7], rescale at [8]

    float4 vc  = vsrc[c];
    float4 acc = make_float4(0.f, 0.f, 0.f, 0.f);
    float m = __uint_as_float(NINFU);
    float s = 0.0f;
    size_t rbase = (size_t)blockIdx.x * 8 * macro_iters;

    for (int it = 0; it < macro_iters; it++) {
        // ---- A: 8 independent coalesced row loads + partial dots ----
        const float4* p = X + (rbase + (size_t)it * 8) * H4 + c;
        float4 x[8];
        #pragma unroll
        for (int g = 0; g < 8; g++) x[g] = p[g * H4];
        #pragma unroll
        for (int g = 0; g < 8; g++)
            sp[g][c] = x[g].x * vc.x + x[g].y * vc.y + x[g].z * vc.z + x[g].w * vc.w;
        __syncthreads();

        // ---- B: 6 warps reduce 8 rows in parallel ----
        for (int g = wid; g < 8; g += 6) {
            float v = 0.0f;
            #pragma unroll
            for (int k = 0; k < 6; k++) v += sp[g][lane + 32 * k];
            v = warpReduceSum(v);
            if (lane == 0) sd[g] = v;
        }
        __syncthreads();

        // ---- C: thread 0 only does the exps (online-softmax update) ----
        if (c == 0) {
            float mn = m;
            #pragma unroll
            for (int g = 0; g < 8; g++) mn = fmaxf(mn, sd[g]);
            float sc = __expf(m - mn);     // exp(-inf)=0 on first iter
            float ls = s * sc;
            #pragma unroll
            for (int g = 0; g < 8; g++) {
                float w = __expf(sd[g] - mn);
                sw[g] = w; ls += w;
            }
            sw[8] = sc; s = ls; m = mn;
        }
        __syncthreads();

        // ---- D: rescale + accumulate (x still in registers) ----
        float sc = sw[8];
        acc.x *= sc; acc.y *= sc; acc.z *= sc; acc.w *= sc;
        #pragma unroll
        for (int g = 0; g < 8; g++) {
            float w = sw[g];
            acc.x += w * x[g].x; acc.y += w * x[g].y;
            acc.z += w * x[g].z; acc.w += w * x[g].w;
        }
    }

    if (c == 0) { g_pm[blockIdx.x] = m; g_ps[blockIdx.x] = s; }
    ((float4*)g_pacc)[blockIdx.x * H4 + c] = acc;
}

// Merge partials -> dst[h] += (sum_w exp(pm[w]-M) * pacc[w][h]) / S
// Each block redundantly computes global M and S (cheap), grid (3, NB/chunk).
__global__ void __launch_bounds__(256)
merge_kernel(float* __restrict__ dst, int NB, int chunk) {
    __shared__ float sm[1024];
    __shared__ float s2[256];
    __shared__ float scoef[64];
    int t = threadIdx.x;
    float ninf = __uint_as_float(NINFU);

    for (int i = t; i < 1024; i += 256) sm[i] = (i < NB) ? g_pm[i] : ninf;
    __syncthreads();
    for (int o = 512; o > 0; o >>= 1) {
        for (int i = t; i < o; i += 256) sm[i] = fmaxf(sm[i], sm[i + o]);
        __syncthreads();
    }
    float M = sm[0];

    float ss = 0.0f;
    for (int i = t; i < NB; i += 256) ss += __expf(g_pm[i] - M) * g_ps[i];
    s2[t] = ss;
    __syncthreads();
    for (int o = 128; o > 0; o >>= 1) {
        if (t < o) s2[t] += s2[t + o];
        __syncthreads();
    }
    float S = s2[0];

    int w0 = blockIdx.y * chunk;
    if (t < chunk) scoef[t] = __expf(g_pm[w0 + t] - M);
    __syncthreads();

    int h = blockIdx.x * 256 + t;
    float a = 0.0f;
    for (int i = 0; i < chunk; i++)
        a += scoef[i] * g_pacc[(size_t)(w0 + i) * H + h];
    atomicAdd(&dst[h], a / S);
}

// v[row] = W[row,:] . ep_   (ep_ normalized, lives in d_out[768:])
__global__ void v_kernel(const float4* __restrict__ W4, const float4* __restrict__ ep) {
    int row  = blockIdx.x * 8 + (threadIdx.x >> 5);
    int lane = threadIdx.x & 31;
    const float4* r = W4 + (size_t)row * H4;
    float p = 0.0f;
    #pragma unroll
    for (int k = 0; k < 6; k++) {
        float4 a = r[lane + 32 * k], b = ep[lane + 32 * k];
        p += a.x * b.x + a.y * b.y + a.z * b.z + a.w * b.w;
    }
    p = warpReduceSum(p);
    if (lane == 0) g_v[row] = p;
}

// ---------------- launch ----------------
extern "C" void kernel_launch(void* const* d_in, const int* in_sizes, int n_in,
                              void* d_out, int out_size) {
    const float *fact = nullptr, *ep = nullptr, *W = nullptr;
    int N = 0, M = 0;
    for (int i = 0; i < n_in; i++) {
        long long sz = in_sizes[i];
        if (sz == (long long)H * H)           W    = (const float*)d_in[i];
        else if (sz == (long long)4096 * H) { ep   = (const float*)d_in[i]; M = 4096; }
        else                                { fact = (const float*)d_in[i]; N = (int)(sz / H); }
    }
    const float4* fact4 = (const float4*)fact;
    const float4* ep4   = (const float4*)ep;
    float* out = (float*)d_out;

    init_kernel<<<1, 768>>>(out);
    colmax_kernel<<<1024, 192>>>(fact4, N * H4);           // pass 1 over fact
    qw_kernel<<<dim3(3, 24), 256>>>(W);                    // qw = fact_Q @ W

    fused_kernel<false><<<512, 192>>>(ep4, 1);             // ep pass (vsrc = g_qw)
    merge_kernel<<<dim3(3, 8), 256>>>(out + H, 512, 64);   // -> ep_ (normalized) in out[768:]

    v_kernel<<<96, 256>>>((const float4*)W,
                          (const float4*)(out + H));       // v = W @ ep_

    fused_kernel<true><<<1024, 192>>>(fact4, 4);           // pass 2 over fact (vsrc = g_v)
    merge_kernel<<<dim3(3, 16), 256>>>(out, 1024, 64);     // -> fact_ in out[0:768]
}

// round 7
// speedup vs baseline: 1.6047x; 1.1154x over previous
#include <cuda_runtime.h>

#define H    768
#define H4   192
#define NT   192           // threads per block (one per float4 column)
#define NB   592           // 148 SMs x 4 blocks -- all co-resident by construction
#define NINFU 0xff800000u

// ---------------- scratch (__device__ globals: allocation-free) ----------------
__device__ __align__(16) float g_colmax[H];
__device__ __align__(16) float g_qw[H];
__device__ __align__(16) float g_v[H];
__device__ __align__(16) float g_ep[H];
__device__ float g_pm[NB], g_ps[NB];
__device__ __align__(16) float g_pacc[NB * H];
__device__ unsigned g_cnt = 0, g_gen = 0;     // software grid barrier state

// ---------------- helpers ----------------
__device__ __forceinline__ void atomicMaxFloat(float* addr, float val) {
    if (val >= 0.0f) atomicMax((int*)addr, __float_as_int(val));
    else             atomicMin((unsigned int*)addr, __float_as_uint(val));
}
__device__ __forceinline__ float warpReduceSum(float v) {
    #pragma unroll
    for (int o = 16; o; o >>= 1) v += __shfl_xor_sync(0xffffffffu, v, o);
    return v;
}

// sense-reversing software grid barrier; valid because all NB blocks are resident.
__device__ __forceinline__ void gsync() {
    __syncthreads();
    if (threadIdx.x == 0) {
        __threadfence();
        unsigned gen = atomicAdd(&g_gen, 0u);
        if (atomicAdd(&g_cnt, 1u) == NB - 1u) {
            atomicExch(&g_cnt, 0u);
            __threadfence();
            atomicAdd(&g_gen, 1u);
        } else {
            while (atomicAdd(&g_gen, 0u) == gen) __nanosleep(64);
            __threadfence();
        }
    }
    __syncthreads();
}

// One 8-row fused tile: loads -> partial dots -> row reduce -> online softmax
// (exps on t0 only) -> rescale+accumulate. No trailing sync needed (proved by
// the barrier placement: next iter's sp write is fenced by its own sync).
__device__ __forceinline__ void tile8(const float4* __restrict__ X, float4 vc, int tile,
                                      float& m, float& s, float4& acc,
                                      float (*sp)[H4], float* sd, float* sw,
                                      int t, int wid, int lane) {
    const float4* p = X + (size_t)tile * 8 * H4 + t;
    float4 x[8];
    #pragma unroll
    for (int g = 0; g < 8; g++) x[g] = p[g * H4];
    #pragma unroll
    for (int g = 0; g < 8; g++)
        sp[g][t] = x[g].x * vc.x + x[g].y * vc.y + x[g].z * vc.z + x[g].w * vc.w;
    __syncthreads();

    for (int g = wid; g < 8; g += 6) {
        float v = 0.0f;
        #pragma unroll
        for (int k = 0; k < 6; k++) v += sp[g][lane + 32 * k];
        v = warpReduceSum(v);
        if (lane == 0) sd[g] = v;
    }
    __syncthreads();

    if (t == 0) {
        float mn = m;
        #pragma unroll
        for (int g = 0; g < 8; g++) mn = fmaxf(mn, sd[g]);
        float sc = __expf(m - mn);          // exp(-inf)=0 on first tile
        float ls = s * sc;
        #pragma unroll
        for (int g = 0; g < 8; g++) { float w = __expf(sd[g] - mn); sw[g] = w; ls += w; }
        sw[8] = sc; s = ls; m = mn;
    }
    __syncthreads();

    float sc = sw[8];
    acc.x *= sc; acc.y *= sc; acc.z *= sc; acc.w *= sc;
    #pragma unroll
    for (int g = 0; g < 8; g++) {
        float w = sw[g];
        acc.x += w * x[g].x; acc.y += w * x[g].y;
        acc.z += w * x[g].z; acc.w += w * x[g].w;
    }
}

// Softmax-merge of nparts partials into dst[h] (atomicAdd; dst pre-zeroed).
// 32 blocks: (b&3) = h-group of 192, (b>>2) = partial-chunk of `chunk`.
// Each block redundantly computes global M and S (cheap, deterministic).
__device__ __forceinline__ void merge_phase(float* dst, float* dst2, int nparts, int chunk,
                                            int b, int t, float* spf, float* sred) {
    float ninf = __uint_as_float(NINFU);
    float lm = ninf;
    for (int i = t; i < nparts; i += NT) lm = fmaxf(lm, g_pm[i]);
    sred[t] = lm;
    __syncthreads();
    if (t == 0) {
        float M = sred[0];
        for (int i = 1; i < NT; i++) M = fmaxf(M, sred[i]);
        sred[NT] = M;
    }
    __syncthreads();
    float M = sred[NT];

    float ls = 0.0f;
    for (int i = t; i < nparts; i += NT) ls += __expf(g_pm[i] - M) * g_ps[i];
    sred[t] = ls;
    __syncthreads();
    if (t == 0) {
        float S = 0.0f;
        for (int i = 0; i < NT; i++) S += sred[i];
        sred[NT + 1] = S;
    }
    __syncthreads();
    float S = sred[NT + 1];

    int w0 = (b >> 2) * chunk;
    for (int i = t; i < chunk; i += NT) spf[i] = __expf(g_pm[w0 + i] - M);
    __syncthreads();

    int h = (b & 3) * NT + t;
    float a = 0.0f;
    #pragma unroll 4
    for (int i = 0; i < chunk; i++)
        a += spf[i] * g_pacc[(size_t)(w0 + i) * H + h];
    a /= S;
    atomicAdd(&dst[h], a);
    if (dst2) atomicAdd(&dst2[h], a);
    __syncthreads();
}

// ---------------- the single persistent kernel ----------------
__global__ void __launch_bounds__(NT, 4)
mega_kernel(const float4* __restrict__ fact4, const float4* __restrict__ ep4,
            const float* __restrict__ W, float* __restrict__ out, int N, int M) {
    int b = blockIdx.x, t = threadIdx.x;
    int lane = t & 31, wid = t >> 5;
    float ninf = __uint_as_float(NINFU);

    __shared__ float sp[8][H4];        // 6 KB, reused by merges as flat buffer
    __shared__ float sd[8];
    __shared__ float sw[9];
    __shared__ float sred[NT + 2];
    float* spf = &sp[0][0];            // 1536 floats >= max chunk

    // ---- P0: init (block 0) ----
    if (b == 0) {
        for (int i = t; i < H; i += NT) {
            g_colmax[i] = ninf; g_qw[i] = 0.0f; g_ep[i] = 0.0f;
            out[i] = 0.0f; out[i + H] = 0.0f;
        }
    }
    gsync();   // B1

    // ---- P1: column max over fact (96 MB, forced MLP=8) ----
    {
        int n4 = N * H4;
        const int stride = NB * NT;
        int i = b * NT + t;
        float4 m4 = make_float4(ninf, ninf, ninf, ninf);
        for (; i + 7 * stride < n4; i += 8 * stride) {
            float4 x[8];
            #pragma unroll
            for (int g = 0; g < 8; g++) x[g] = fact4[i + g * stride];
            #pragma unroll
            for (int g = 0; g < 8; g++) {
                m4.x = fmaxf(m4.x, x[g].x); m4.y = fmaxf(m4.y, x[g].y);
                m4.z = fmaxf(m4.z, x[g].z); m4.w = fmaxf(m4.w, x[g].w);
            }
        }
        for (; i < n4; i += stride) {
            float4 x = fact4[i];
            m4.x = fmaxf(m4.x, x.x); m4.y = fmaxf(m4.y, x.y);
            m4.z = fmaxf(m4.z, x.z); m4.w = fmaxf(m4.w, x.w);
        }
        int c = t * 4;                 // column class fixed per thread
        atomicMaxFloat(&g_colmax[c + 0], m4.x);
        atomicMaxFloat(&g_colmax[c + 1], m4.y);
        atomicMaxFloat(&g_colmax[c + 2], m4.z);
        atomicMaxFloat(&g_colmax[c + 3], m4.w);
    }
    gsync();   // B2

    // ---- P2: qw[j] = sum_h colmax[h] * W[h,j]  (96 blocks) ----
    if (b < 96) {
        int j = (b & 3) * NT + t, h0 = (b >> 2) * 32;
        float a = 0.0f;
        #pragma unroll 8
        for (int i = 0; i < 32; i++)
            a += g_colmax[h0 + i] * W[(size_t)(h0 + i) * H + j];
        atomicAdd(&g_qw[j], a);
    }
    gsync();   // B3

    // ---- P3: elements_p fused pass (512 blocks x 8 rows) ----
    if (b < M / 8) {
        float4 vc = ((const float4*)g_qw)[t];
        float m = ninf, s = 0.0f;
        float4 acc = make_float4(0.f, 0.f, 0.f, 0.f);
        tile8(ep4, vc, b, m, s, acc, sp, sd, sw, t, wid, lane);
        if (t == 0) { g_pm[b] = m; g_ps[b] = s; }
        ((float4*)g_pacc)[b * H4 + t] = acc;
    }
    gsync();   // B4

    // ---- P4: merge ep partials -> g_ep (and out[768:]) ----
    if (b < 32) merge_phase(g_ep, out + H, M / 8, (M / 8) / 8, b, t, spf, sred);
    gsync();   // B5

    // ---- P5: v[row] = W[row,:] . ep_  (128 blocks x 6 warps) ----
    if (b < 128) {
        int row = b * 6 + wid;
        const float4* r = (const float4*)(W + (size_t)row * H);
        float p = 0.0f;
        #pragma unroll
        for (int k = 0; k < 6; k++) {
            float4 a = r[lane + 32 * k];
            float4 e = ((const float4*)g_ep)[lane + 32 * k];
            p += a.x * e.x + a.y * e.y + a.z * e.z + a.w * e.w;
        }
        p = warpReduceSum(p);
        if (lane == 0) g_v[row] = p;
    }
    gsync();   // B6

    // ---- P6: fact fused pass (all 592 blocks, strided 8-row tiles) ----
    {
        float4 vc = ((const float4*)g_v)[t];
        float m = ninf, s = 0.0f;
        float4 acc = make_float4(0.f, 0.f, 0.f, 0.f);
        int ntiles = N / 8;
        for (int tile = b; tile < ntiles; tile += NB)
            tile8(fact4, vc, tile, m, s, acc, sp, sd, sw, t, wid, lane);
        if (t == 0) { g_pm[b] = m; g_ps[b] = s; }
        ((float4*)g_pacc)[b * H4 + t] = acc;
    }
    gsync();   // B7

    // ---- P7: merge fact partials -> out[0:768] ----
    if (b < 32) merge_phase(out, nullptr, NB, NB / 8, b, t, spf, sred);
}

// ---------------- launch ----------------
extern "C" void kernel_launch(void* const* d_in, const int* in_sizes, int n_in,
                              void* d_out, int out_size) {
    const float *fact = nullptr, *ep = nullptr, *W = nullptr;
    int N = 0, M = 0;
    for (int i = 0; i < n_in; i++) {
        long long sz = in_sizes[i];
        if (sz == (long long)H * H)           W    = (const float*)d_in[i];
        else if (sz == (long long)4096 * H) { ep   = (const float*)d_in[i]; M = 4096; }
        else                                { fact = (const float*)d_in[i]; N = (int)(sz / H); }
    }
    mega_kernel<<<NB, NT>>>((const float4*)fact, (const float4*)ep, W,
                            (float*)d_out, N, M);
}